// round 3
// baseline (speedup 1.0000x reference)
#include <cuda_runtime.h>
#include <cstdint>

// ---------------------------------------------------------------------------
// HeteroGraphConv, D=128 fixed.
// Pipeline:
//   aggr_a = x_a; aggr_b = x_b                       (memcpyAsync D2D, residual)
//   H = relu(x_a @ w1_ab + b1_ab)                    (gemm mode0)
//   T = H @ w2_ab + b2_ab                            (gemm mode1)
//   aggr_b += scatter_add(T[src]*ea over dst)        (edge kernel, red.v4.f32)
//   (same for b->a)
//   out_a = relu(LN(aggr_a @ wu_a + bu_a)*g + be)    (gemm mode2, fused LN)
//   out_b = ...
// ---------------------------------------------------------------------------

#define D128 128
#define BM 64
#define BK 8
#define MAXN 50176  // capacity rows for scratch (>= 50000)

// Scratch (allocation-free rule: __device__ globals)
__device__ float g_H[MAXN * D128];
__device__ float g_T[MAXN * D128];
__device__ float g_aggr_a[MAXN * D128];
__device__ float g_aggr_b[MAXN * D128];

// MODE: 0 = bias+relu, 1 = bias, 2 = bias + LayerNorm(g,be) + relu
template <int MODE>
__global__ __launch_bounds__(256, 4)
void gemm128_kernel(const float* __restrict__ A,   // [M,128]
                    const float* __restrict__ W,   // [128,128] row-major (k,n)
                    const float* __restrict__ bias,
                    const float* __restrict__ gamma,
                    const float* __restrict__ beta,
                    float* __restrict__ C,         // [M,128]
                    int M)
{
    __shared__ float As[BK][BM];     // A^T tile: As[k][m]
    __shared__ float Ws[BK][D128];   // W tile:   Ws[k][n]

    const int tid = threadIdx.x;
    const int tx  = tid & 31;        // lane: owns cols tx*4 .. tx*4+3
    const int ty  = tid >> 5;        // warp: owns rows ty*8 .. ty*8+7
    const int row0 = blockIdx.x * BM;

    float acc[8][4];
    #pragma unroll
    for (int i = 0; i < 8; i++)
        #pragma unroll
        for (int j = 0; j < 4; j++) acc[i][j] = 0.0f;

    for (int k0 = 0; k0 < D128; k0 += BK) {
        // Load A tile: 64 rows x 8 cols = 128 float4, threads 0..127
        if (tid < 128) {
            int r  = tid >> 1;              // 0..63
            int c4 = (tid & 1) * 4;         // 0 or 4
            int grow = row0 + r;
            float4 v = make_float4(0.f, 0.f, 0.f, 0.f);
            if (grow < M)
                v = *reinterpret_cast<const float4*>(A + (size_t)grow * D128 + k0 + c4);
            As[c4 + 0][r] = v.x;
            As[c4 + 1][r] = v.y;
            As[c4 + 2][r] = v.z;
            As[c4 + 3][r] = v.w;
        }
        // Load W tile: 8 rows x 128 cols = 256 float4, all 256 threads
        {
            int r  = tid >> 5;              // 0..7
            int c4 = (tid & 31) * 4;
            *reinterpret_cast<float4*>(&Ws[r][c4]) =
                *reinterpret_cast<const float4*>(W + (size_t)(k0 + r) * D128 + c4);
        }
        __syncthreads();

        #pragma unroll
        for (int kk = 0; kk < BK; kk++) {
            float4 a0 = *reinterpret_cast<const float4*>(&As[kk][ty * 8]);
            float4 a1 = *reinterpret_cast<const float4*>(&As[kk][ty * 8 + 4]);
            float4 w  = *reinterpret_cast<const float4*>(&Ws[kk][tx * 4]);
            float av[8] = {a0.x, a0.y, a0.z, a0.w, a1.x, a1.y, a1.z, a1.w};
            #pragma unroll
            for (int i = 0; i < 8; i++) {
                acc[i][0] = fmaf(av[i], w.x, acc[i][0]);
                acc[i][1] = fmaf(av[i], w.y, acc[i][1]);
                acc[i][2] = fmaf(av[i], w.z, acc[i][2]);
                acc[i][3] = fmaf(av[i], w.w, acc[i][3]);
            }
        }
        __syncthreads();
    }

    // Epilogue
    float4 bv = *reinterpret_cast<const float4*>(bias + tx * 4);

    if (MODE == 0) {  // bias + relu
        #pragma unroll
        for (int i = 0; i < 8; i++) {
            int grow = row0 + ty * 8 + i;
            if (grow < M) {
                float4 o;
                o.x = fmaxf(acc[i][0] + bv.x, 0.f);
                o.y = fmaxf(acc[i][1] + bv.y, 0.f);
                o.z = fmaxf(acc[i][2] + bv.z, 0.f);
                o.w = fmaxf(acc[i][3] + bv.w, 0.f);
                *reinterpret_cast<float4*>(C + (size_t)grow * D128 + tx * 4) = o;
            }
        }
    } else if (MODE == 1) {  // bias only
        #pragma unroll
        for (int i = 0; i < 8; i++) {
            int grow = row0 + ty * 8 + i;
            if (grow < M) {
                float4 o;
                o.x = acc[i][0] + bv.x;
                o.y = acc[i][1] + bv.y;
                o.z = acc[i][2] + bv.z;
                o.w = acc[i][3] + bv.w;
                *reinterpret_cast<float4*>(C + (size_t)grow * D128 + tx * 4) = o;
            }
        }
    } else {  // bias + LayerNorm + relu. Each warp owns full 128-col rows.
        float4 gv = *reinterpret_cast<const float4*>(gamma + tx * 4);
        float4 ev = *reinterpret_cast<const float4*>(beta  + tx * 4);
        #pragma unroll
        for (int i = 0; i < 8; i++) {
            float h0 = acc[i][0] + bv.x;
            float h1 = acc[i][1] + bv.y;
            float h2 = acc[i][2] + bv.z;
            float h3 = acc[i][3] + bv.w;
            // mean
            float s = h0 + h1 + h2 + h3;
            #pragma unroll
            for (int off = 16; off > 0; off >>= 1)
                s += __shfl_xor_sync(0xFFFFFFFFu, s, off);
            float mu = s * (1.0f / 128.0f);
            // variance (two-pass, matches reference formula)
            float d0 = h0 - mu, d1 = h1 - mu, d2 = h2 - mu, d3 = h3 - mu;
            float q = d0 * d0 + d1 * d1 + d2 * d2 + d3 * d3;
            #pragma unroll
            for (int off = 16; off > 0; off >>= 1)
                q += __shfl_xor_sync(0xFFFFFFFFu, q, off);
            float rstd = rsqrtf(q * (1.0f / 128.0f) + 1e-5f);
            int grow = row0 + ty * 8 + i;
            if (grow < M) {
                float4 o;
                o.x = fmaxf(d0 * rstd * gv.x + ev.x, 0.f);
                o.y = fmaxf(d1 * rstd * gv.y + ev.y, 0.f);
                o.z = fmaxf(d2 * rstd * gv.z + ev.z, 0.f);
                o.w = fmaxf(d3 * rstd * gv.w + ev.w, 0.f);
                *reinterpret_cast<float4*>(C + (size_t)grow * D128 + tx * 4) = o;
            }
        }
    }
}

// One warp per edge: gather 128 floats of t[src], scale by ea, vector-red into aggr[dst].
__global__ __launch_bounds__(256)
void edge_scatter_kernel(const float* __restrict__ t,
                         const int* __restrict__ src,
                         const int* __restrict__ dst,
                         const float* __restrict__ ea,
                         float* __restrict__ aggr,
                         int E)
{
    int wid  = (blockIdx.x * blockDim.x + threadIdx.x) >> 5;
    int lane = threadIdx.x & 31;
    if (wid >= E) return;
    int s = src[wid];
    int d = dst[wid];
    float w = ea[wid];
    float4 v = *reinterpret_cast<const float4*>(t + (size_t)s * D128 + lane * 4);
    v.x *= w; v.y *= w; v.z *= w; v.w *= w;
    float* p = aggr + (size_t)d * D128 + lane * 4;
    asm volatile("red.global.add.v4.f32 [%0], {%1,%2,%3,%4};"
                 :: "l"(p), "f"(v.x), "f"(v.y), "f"(v.z), "f"(v.w)
                 : "memory");
}

extern "C" void kernel_launch(void* const* d_in, const int* in_sizes, int n_in,
                              void* d_out, int out_size)
{
    const float* x_a   = (const float*)d_in[0];
    const float* x_b   = (const float*)d_in[1];
    const int*   ei_ab = (const int*)  d_in[2];   // [2,E]
    const float* ea_ab = (const float*)d_in[3];
    const int*   ei_ba = (const int*)  d_in[4];
    const float* ea_ba = (const float*)d_in[5];
    const float* w1_ab = (const float*)d_in[6];
    const float* b1_ab = (const float*)d_in[7];
    const float* w2_ab = (const float*)d_in[8];
    const float* b2_ab = (const float*)d_in[9];
    const float* w1_ba = (const float*)d_in[10];
    const float* b1_ba = (const float*)d_in[11];
    const float* w2_ba = (const float*)d_in[12];
    const float* b2_ba = (const float*)d_in[13];
    const float* wu_a  = (const float*)d_in[14];
    const float* bu_a  = (const float*)d_in[15];
    const float* g_a   = (const float*)d_in[16];
    const float* be_a  = (const float*)d_in[17];
    const float* wu_b  = (const float*)d_in[18];
    const float* bu_b  = (const float*)d_in[19];
    const float* g_b   = (const float*)d_in[20];
    const float* be_b  = (const float*)d_in[21];

    const int NA = in_sizes[0] / D128;
    const int NB = in_sizes[1] / D128;
    const int E_ab = in_sizes[3];
    const int E_ba = in_sizes[5];

    float* H = nullptr; float* T = nullptr; float* Aa = nullptr; float* Ab = nullptr;
    cudaGetSymbolAddress((void**)&H,  g_H);
    cudaGetSymbolAddress((void**)&T,  g_T);
    cudaGetSymbolAddress((void**)&Aa, g_aggr_a);
    cudaGetSymbolAddress((void**)&Ab, g_aggr_b);

    float* out = (float*)d_out;

    const int blkA = (NA + BM - 1) / BM;
    const int blkB = (NB + BM - 1) / BM;

    // Residual init: aggr = x
    cudaMemcpyAsync(Aa, x_a, (size_t)NA * D128 * sizeof(float), cudaMemcpyDeviceToDevice, 0);
    cudaMemcpyAsync(Ab, x_b, (size_t)NB * D128 * sizeof(float), cudaMemcpyDeviceToDevice, 0);

    // a -> b
    gemm128_kernel<0><<<blkA, 256>>>(x_a, w1_ab, b1_ab, nullptr, nullptr, H, NA);
    gemm128_kernel<1><<<blkA, 256>>>(H,   w2_ab, b2_ab, nullptr, nullptr, T, NA);
    {
        int blocks = (E_ab + 7) / 8;  // 8 warps/block
        edge_scatter_kernel<<<blocks, 256>>>(T, ei_ab, ei_ab + E_ab, ea_ab, Ab, E_ab);
    }

    // b -> a
    gemm128_kernel<0><<<blkB, 256>>>(x_b, w1_ba, b1_ba, nullptr, nullptr, H, NB);
    gemm128_kernel<1><<<blkB, 256>>>(H,   w2_ba, b2_ba, nullptr, nullptr, T, NB);
    {
        int blocks = (E_ba + 7) / 8;
        edge_scatter_kernel<<<blocks, 256>>>(T, ei_ba, ei_ba + E_ba, ea_ba, Aa, E_ba);
    }

    // Node updates (fused GEMM + LayerNorm + ReLU)
    gemm128_kernel<2><<<blkA, 256>>>(Aa, wu_a, bu_a, g_a, be_a, out, NA);
    gemm128_kernel<2><<<blkB, 256>>>(Ab, wu_b, bu_b, g_b, be_b, out + (size_t)NA * D128, NB);
}